// round 13
// baseline (speedup 1.0000x reference)
#include <cuda_runtime.h>
#include <cuda_fp16.h>
#include <cstdint>
#include <math.h>
#include <mma.h>

using namespace nvcuda;

#define B_  256
#define T_  128
#define X_  256
#define H_  1024

#define BN  64
#define BLD (BN + 8)                  // 72

// ---------------- device scratch ----------------
__device__ float  g_y   [B_ * X_];
__device__ __half g_yh  [B_ * X_];
__device__ float  g_h0f [B_ * H_];
__device__ __half g_a   [B_ * H_];
__device__ __half g_b1  [B_ * H_];
__device__ __half g_b2  [B_ * H_];
__device__ __half g_b3  [B_ * H_];
__device__ float  g_bcat[1280];

#define WH_IN   0
#define WH_H    (256 * 1024)
#define WH_OUTA (WH_H + 3 * 1024 * 1024)
#define WH_CAT  (WH_OUTA + 1024 * 256)
#define WH_TOT  (WH_CAT + 1024 * 1280)
__device__ __half g_wh[WH_TOT];

#define CP16(dst, src) \
    asm volatile("cp.async.cg.shared.global [%0], [%1], 16;" :: "r"(dst), "l"(src))
#define CP_COMMIT() asm volatile("cp.async.commit_group;" ::: "memory")

__device__ __forceinline__ float tanhfast(float x) {
    float y;
    asm("tanh.approx.f32 %0, %1;" : "=f"(y) : "f"(x));
    return y;
}

// ---------------- setup kernels ----------------
__global__ void node_init_kernel(const float* __restrict__ x, float* __restrict__ out) {
    int i = blockIdx.x * blockDim.x + threadIdx.x;
    float v = x[i];
    g_y[i]  = v;
    g_yh[i] = __float2half_rn(v);
    int b = i / X_, c = i % X_;
    out[(size_t)b * T_ * X_ + c] = v;
}

__global__ void cvt_kernel(const float* __restrict__ src, __half* __restrict__ dst, int n) {
    int i = blockIdx.x * blockDim.x + threadIdx.x;
    if (i < n) dst[i] = __float2half_rn(src[i]);
}

__global__ void pack_wout_kernel(const float* __restrict__ W_out, __half* __restrict__ wcat) {
    int i = blockIdx.x * blockDim.x + threadIdx.x;    // 1024*256
    int k = i >> 8, n = i & 255;
    wcat[k * 1280 + n] = __float2half_rn(W_out[k * 256 + n]);
}

__global__ void bcat_kernel(const float* __restrict__ b_out, const float* __restrict__ W_in,
                            float* __restrict__ bcat) {
    int n = blockIdx.x * blockDim.x + threadIdx.x;
    if (n >= 1280) return;
    if (n < 256) bcat[n] = b_out[n];
    else {
        int c = n - 256;
        float s = 0.f;
        for (int k = 0; k < 256; k++) s += b_out[k] * W_in[k * 1024 + c];
        bcat[n] = s;
    }
}

// ---------------- WMMA fp16 GEMM, templated tile/BK/stages ----------------
// MODE 0: CoutH = tanh(val + bias)   (hidden)
// MODE 1: fused out: bn<256 -> y += dt*val, store out; else h0f += dt*val, a = tanh
// MODE 2: CoutH = val (no bias)      (combo setup)
// MODE 3: h0f = val + bias; a = tanh (initial in-layer)
template <int TBM, int BKT, int NSTG, int MODE>
__global__ void __launch_bounds__(256, 1) gemm_k(
    const __half* __restrict__ A, const __half* __restrict__ W,
    const float* __restrict__ bias, __half* __restrict__ CoutH,
    int K, int N, int ldc,
    float* __restrict__ gy, float* __restrict__ h0f, __half* __restrict__ aout,
    float* __restrict__ outp, const float* __restrict__ ts, int t)
{
    extern __shared__ __half smem[];
    constexpr int ALD = BKT + 8;
    constexpr int AST = TBM * ALD;
    constexpr int BST = BKT * BLD;
    constexpr int SH  = AST + BST;

    const int tid = threadIdx.x;
    const int bm  = blockIdx.y * TBM;
    const int bn  = blockIdx.x * BN;
    const int w   = tid >> 5;
    const int wm  = (TBM == 32) ? (w & 1) : (w & 3);
    const int wn  = (TBM == 32) ? (w >> 1) : (w >> 2);

    wmma::fragment<wmma::accumulator, 16, 16, 16, float> c0, c1;
    wmma::fill_fragment(c0, 0.0f);
    if (TBM == 64) wmma::fill_fragment(c1, 0.0f);

    const int NIT = K / BKT;

    auto loadStage = [&](int it) {
        if (it < NIT) {
            const int k0 = it * BKT;
            __half* As = smem + (it % NSTG) * SH;
            uint32_t asb = (uint32_t)__cvta_generic_to_shared(As);
            uint32_t bsb = (uint32_t)__cvta_generic_to_shared(As + AST);
            constexpr int ACH = TBM * BKT / 8 / 256;
            constexpr int RW  = BKT / 8;             // chunks per A row
            #pragma unroll
            for (int i = 0; i < ACH; i++) {
                int id = tid + i * 256;
                int r = id / RW, c8 = id % RW;
                CP16(asb + (uint32_t)(r * ALD + c8 * 8) * 2,
                     A + (size_t)(bm + r) * K + k0 + c8 * 8);
            }
            constexpr int BCH = BKT * BN / 8 / 256;
            #pragma unroll
            for (int i = 0; i < BCH; i++) {
                int id = tid + i * 256;
                int r = id >> 3, c8 = id & 7;
                CP16(bsb + (uint32_t)(r * BLD + c8 * 8) * 2,
                     W + (size_t)(k0 + r) * N + bn + c8 * 8);
            }
        }
        CP_COMMIT();
    };

    #pragma unroll
    for (int s = 0; s < NSTG - 1; s++) loadStage(s);

    for (int it = 0; it < NIT; it++) {
        if (NSTG == 4) asm volatile("cp.async.wait_group 2;" ::: "memory");
        else           asm volatile("cp.async.wait_group 1;" ::: "memory");
        __syncthreads();

        const __half* Ab = smem + (it % NSTG) * SH;
        const __half* Bb = Ab + AST;

        #pragma unroll
        for (int kf = 0; kf < BKT / 16; kf++) {
            wmma::fragment<wmma::matrix_a, 16, 16, 16, __half, wmma::row_major> a0;
            wmma::load_matrix_sync(a0, Ab + (wm * 16) * ALD + kf * 16, ALD);
            if (TBM == 32) {
                wmma::fragment<wmma::matrix_b, 16, 16, 16, __half, wmma::row_major> b0;
                wmma::load_matrix_sync(b0, Bb + (kf * 16) * BLD + wn * 16, BLD);
                wmma::mma_sync(c0, a0, b0, c0);
            } else {
                wmma::fragment<wmma::matrix_b, 16, 16, 16, __half, wmma::row_major> b0, b1;
                wmma::load_matrix_sync(b0, Bb + (kf * 16) * BLD + wn * 32 +  0, BLD);
                wmma::load_matrix_sync(b1, Bb + (kf * 16) * BLD + wn * 32 + 16, BLD);
                wmma::mma_sync(c0, a0, b0, c0);
                wmma::mma_sync(c1, a0, b1, c1);
            }
        }
        loadStage(it + NSTG - 1);
    }

    // ---- epilogue ----
    __syncthreads();
    float* E = reinterpret_cast<float*>(smem);   // [TBM][BLD] fp32
    if (TBM == 32) {
        wmma::store_matrix_sync(E + (size_t)(wm * 16) * BLD + wn * 16, c0, BLD, wmma::mem_row_major);
    } else {
        wmma::store_matrix_sync(E + (size_t)(wm * 16) * BLD + wn * 32 +  0, c0, BLD, wmma::mem_row_major);
        wmma::store_matrix_sync(E + (size_t)(wm * 16) * BLD + wn * 32 + 16, c1, BLD, wmma::mem_row_major);
    }
    __syncthreads();

    constexpr int NCH = (TBM == 32) ? 2 : 4;
    const int r     = (TBM == 32) ? (tid >> 3) : (tid >> 2);
    const int cbase = (TBM == 32) ? ((tid & 7) * 8) : ((tid & 3) * 16);

    if (MODE == 1) {
        const float dt = ts[t + 1] - ts[t];
        if (bn < 256) {
            #pragma unroll
            for (int j = 0; j < NCH; j++) {
                int col = cbase + j * 4;
                int n   = bn + col;
                int yi  = (bm + r) * X_ + n;
                float4 bv = *reinterpret_cast<const float4*>(&bias[n]);
                float4 yv = *reinterpret_cast<float4*>(&gy[yi]);
                yv.x += dt * (E[r * BLD + col + 0] + bv.x);
                yv.y += dt * (E[r * BLD + col + 1] + bv.y);
                yv.z += dt * (E[r * BLD + col + 2] + bv.z);
                yv.w += dt * (E[r * BLD + col + 3] + bv.w);
                *reinterpret_cast<float4*>(&gy[yi]) = yv;
                *reinterpret_cast<float4*>(&outp[(size_t)(bm + r) * T_ * X_ +
                                                 (size_t)(t + 1) * X_ + n]) = yv;
            }
        } else {
            #pragma unroll
            for (int j = 0; j < NCH; j++) {
                int col = cbase + j * 4;
                int n   = bn + col;
                int hi  = (bm + r) * H_ + (n - 256);
                float4 bv = *reinterpret_cast<const float4*>(&bias[n]);
                float4 hv = *reinterpret_cast<float4*>(&h0f[hi]);
                hv.x += dt * (E[r * BLD + col + 0] + bv.x);
                hv.y += dt * (E[r * BLD + col + 1] + bv.y);
                hv.z += dt * (E[r * BLD + col + 2] + bv.z);
                hv.w += dt * (E[r * BLD + col + 3] + bv.w);
                *reinterpret_cast<float4*>(&h0f[hi]) = hv;
                __half2 p0 = __halves2half2(__float2half_rn(tanhfast(hv.x)), __float2half_rn(tanhfast(hv.y)));
                __half2 p1 = __halves2half2(__float2half_rn(tanhfast(hv.z)), __float2half_rn(tanhfast(hv.w)));
                uint2 pk = make_uint2(*reinterpret_cast<uint32_t*>(&p0),
                                      *reinterpret_cast<uint32_t*>(&p1));
                *reinterpret_cast<uint2*>(&aout[hi]) = pk;
            }
        }
    } else {
        #pragma unroll
        for (int j = 0; j < NCH; j++) {
            int col = cbase + j * 4;
            float4 v = *reinterpret_cast<float4*>(&E[r * BLD + col]);
            if (MODE == 0 || MODE == 3) {
                float4 bv = *reinterpret_cast<const float4*>(&bias[bn + col]);
                v.x += bv.x; v.y += bv.y; v.z += bv.z; v.w += bv.w;
            }
            if (MODE == 0) {
                __half2 p0 = __halves2half2(__float2half_rn(tanhfast(v.x)), __float2half_rn(tanhfast(v.y)));
                __half2 p1 = __halves2half2(__float2half_rn(tanhfast(v.z)), __float2half_rn(tanhfast(v.w)));
                uint2 pk = make_uint2(*reinterpret_cast<uint32_t*>(&p0),
                                      *reinterpret_cast<uint32_t*>(&p1));
                *reinterpret_cast<uint2*>(&CoutH[(size_t)(bm + r) * ldc + bn + col]) = pk;
            } else if (MODE == 2) {
                __half2 p0 = __halves2half2(__float2half_rn(v.x), __float2half_rn(v.y));
                __half2 p1 = __halves2half2(__float2half_rn(v.z), __float2half_rn(v.w));
                uint2 pk = make_uint2(*reinterpret_cast<uint32_t*>(&p0),
                                      *reinterpret_cast<uint32_t*>(&p1));
                *reinterpret_cast<uint2*>(&CoutH[(size_t)(bm + r) * ldc + bn + col]) = pk;
            } else {  // MODE 3
                int hi = (bm + r) * ldc + bn + col;
                *reinterpret_cast<float4*>(&h0f[hi]) = v;
                __half2 p0 = __halves2half2(__float2half_rn(tanhfast(v.x)), __float2half_rn(tanhfast(v.y)));
                __half2 p1 = __halves2half2(__float2half_rn(tanhfast(v.z)), __float2half_rn(tanhfast(v.w)));
                uint2 pk = make_uint2(*reinterpret_cast<uint32_t*>(&p0),
                                      *reinterpret_cast<uint32_t*>(&p1));
                *reinterpret_cast<uint2*>(&aout[hi]) = pk;
            }
        }
    }
}

// smem sizes
#define SMEM_OF(TBM, BKT, NSTG) ((NSTG) * ((TBM) * ((BKT) + 8) + (BKT) * BLD) * 2)

// ---------------- host ----------------
extern "C" void kernel_launch(void* const* d_in, const int* in_sizes, int n_in,
                              void* d_out, int out_size)
{
    const float* x     = (const float*)d_in[0];
    const float* ts    = (const float*)d_in[1];
    const float* W_in  = (const float*)d_in[2];
    const float* b_in  = (const float*)d_in[3];
    const float* W_h   = (const float*)d_in[4];
    const float* b_h   = (const float*)d_in[5];
    const float* W_out = (const float*)d_in[6];
    const float* b_out = (const float*)d_in[7];
    float* out = (float*)d_out;

    float  *py, *ph0f, *pbcat;
    __half *pyh, *pa, *pb1, *pb2, *pb3, *pwh;
    cudaGetSymbolAddress((void**)&py,   g_y);
    cudaGetSymbolAddress((void**)&pyh,  g_yh);
    cudaGetSymbolAddress((void**)&ph0f, g_h0f);
    cudaGetSymbolAddress((void**)&pa,   g_a);
    cudaGetSymbolAddress((void**)&pb1,  g_b1);
    cudaGetSymbolAddress((void**)&pb2,  g_b2);
    cudaGetSymbolAddress((void**)&pb3,  g_b3);
    cudaGetSymbolAddress((void**)&pbcat, g_bcat);
    cudaGetSymbolAddress((void**)&pwh,  g_wh);

    constexpr int SM_H = SMEM_OF(32, 256, 4);   // 215040
    constexpr int SM_F = SMEM_OF(64, 256, 3);   // 211968
    constexpr int SM_S = SMEM_OF(32, 128, 4);   // 108544

    cudaFuncSetAttribute(gemm_k<32, 256, 4, 0>, cudaFuncAttributeMaxDynamicSharedMemorySize, SM_H);
    cudaFuncSetAttribute(gemm_k<64, 256, 3, 1>, cudaFuncAttributeMaxDynamicSharedMemorySize, SM_F);
    cudaFuncSetAttribute(gemm_k<32, 128, 4, 2>, cudaFuncAttributeMaxDynamicSharedMemorySize, SM_S);
    cudaFuncSetAttribute(gemm_k<32, 128, 4, 3>, cudaFuncAttributeMaxDynamicSharedMemorySize, SM_S);

    // ---- one-time setup ----
    cvt_kernel<<<(256 * 1024 + 255) / 256, 256>>>(W_in,  pwh + WH_IN,   256 * 1024);
    cvt_kernel<<<(3 * 1024 * 1024 + 255) / 256, 256>>>(W_h, pwh + WH_H, 3 * 1024 * 1024);
    cvt_kernel<<<(1024 * 256 + 255) / 256, 256>>>(W_out, pwh + WH_OUTA, 1024 * 256);
    pack_wout_kernel<<<1024, 256>>>(W_out, pwh + WH_CAT);
    bcat_kernel<<<5, 256>>>(b_out, W_in, pbcat);

    // W_combo = W_out @ W_in -> W_cat columns [256, 1280)
    gemm_k<32, 128, 4, 2><<<dim3(16, 32), 256, SM_S>>>(
        pwh + WH_OUTA, pwh + WH_IN, (const float*)nullptr, pwh + WH_CAT + 256,
        256, 1024, 1280,
        (float*)nullptr, (float*)nullptr, (__half*)nullptr, (float*)nullptr,
        (const float*)nullptr, 0);

    node_init_kernel<<<(B_ * X_) / 256, 256>>>(x, out);

    // h0f = x @ W_in + b_in ; a = tanh(h0f)
    gemm_k<32, 128, 4, 3><<<dim3(16, 8), 256, SM_S>>>(
        pyh, pwh + WH_IN, b_in, (__half*)nullptr,
        256, 1024, 1024,
        (float*)nullptr, ph0f, pa, (float*)nullptr, (const float*)nullptr, 0);

    // ---- time loop: 4 plain-launched GEMMs per step ----
    dim3 blk(256);
    dim3 gridH(16, 8);    // hidden: 128 CTAs (TBM=32)
    dim3 gridF(20, 4);    // fused:  80 CTAs (TBM=64), single wave

    const __half* Wh = pwh + WH_H;

    for (int t = 0; t < T_ - 1; t++) {
        gemm_k<32, 256, 4, 0><<<gridH, blk, SM_H>>>(
            pa,  Wh + 0 * 1024 * 1024, b_h + 0 * H_, pb1, 1024, 1024, 1024,
            (float*)nullptr, (float*)nullptr, (__half*)nullptr, (float*)nullptr,
            (const float*)nullptr, 0);
        gemm_k<32, 256, 4, 0><<<gridH, blk, SM_H>>>(
            pb1, Wh + 1 * 1024 * 1024, b_h + 1 * H_, pb2, 1024, 1024, 1024,
            (float*)nullptr, (float*)nullptr, (__half*)nullptr, (float*)nullptr,
            (const float*)nullptr, 0);
        gemm_k<32, 256, 4, 0><<<gridH, blk, SM_H>>>(
            pb2, Wh + 2 * 1024 * 1024, b_h + 2 * H_, pb3, 1024, 1024, 1024,
            (float*)nullptr, (float*)nullptr, (__half*)nullptr, (float*)nullptr,
            (const float*)nullptr, 0);
        gemm_k<64, 256, 3, 1><<<gridF, blk, SM_F>>>(
            pb3, pwh + WH_CAT, pbcat, (__half*)nullptr, 1024, 1280, 0,
            py, ph0f, pa, out, ts, t);
    }
}

// round 14
// speedup vs baseline: 1.0421x; 1.0421x over previous
#include <cuda_runtime.h>
#include <cuda_fp16.h>
#include <cstdint>
#include <math.h>

#define B_  256
#define T_  128
#define X_  256
#define H_  1024

#define BN  64
#define BK  128
#define NSTG 4
#define ALD (BK + 8)                  // 136 halves
#define BLD (BN + 8)                  // 72 halves
#define BST (BK * BLD)                // 9216 halves

// ---------------- device scratch ----------------
__device__ float  g_y   [B_ * X_];
__device__ __half g_yh  [B_ * X_];
__device__ float  g_h0f [B_ * H_];
__device__ __half g_a   [B_ * H_];
__device__ __half g_b1  [B_ * H_];
__device__ __half g_b2  [B_ * H_];
__device__ __half g_b3  [B_ * H_];
__device__ float  g_bcat[1280];

#define WH_IN   0
#define WH_H    (256 * 1024)
#define WH_OUTA (WH_H + 3 * 1024 * 1024)
#define WH_CAT  (WH_OUTA + 1024 * 256)
#define WH_TOT  (WH_CAT + 1024 * 1280)
__device__ __half g_wh[WH_TOT];

#define CP16(dst, src) \
    asm volatile("cp.async.cg.shared.global [%0], [%1], 16;" :: "r"(dst), "l"(src))
#define CP_COMMIT() asm volatile("cp.async.commit_group;" ::: "memory")
#define CP_WAIT2()  asm volatile("cp.async.wait_group 2;" ::: "memory")

__device__ __forceinline__ float tanhfast(float x) {
    float y;
    asm("tanh.approx.f32 %0, %1;" : "=f"(y) : "f"(x));
    return y;
}

__device__ __forceinline__ void ldsm_x4(uint32_t (&d)[4], uint32_t addr) {
    asm volatile("ldmatrix.sync.aligned.m8n8.x4.shared.b16 {%0,%1,%2,%3}, [%4];"
        : "=r"(d[0]), "=r"(d[1]), "=r"(d[2]), "=r"(d[3]) : "r"(addr));
}
__device__ __forceinline__ void ldsm_x4t(uint32_t (&d)[4], uint32_t addr) {
    asm volatile("ldmatrix.sync.aligned.m8n8.x4.trans.shared.b16 {%0,%1,%2,%3}, [%4];"
        : "=r"(d[0]), "=r"(d[1]), "=r"(d[2]), "=r"(d[3]) : "r"(addr));
}
__device__ __forceinline__ void mma16816(float (&c)[4], const uint32_t (&a)[4],
                                         uint32_t b0, uint32_t b1) {
    asm volatile("mma.sync.aligned.m16n8k16.row.col.f32.f16.f16.f32 "
        "{%0,%1,%2,%3}, {%4,%5,%6,%7}, {%8,%9}, {%0,%1,%2,%3};"
        : "+f"(c[0]), "+f"(c[1]), "+f"(c[2]), "+f"(c[3])
        : "r"(a[0]), "r"(a[1]), "r"(a[2]), "r"(a[3]), "r"(b0), "r"(b1));
}

// ---------------- setup kernels ----------------
__global__ void node_init_kernel(const float* __restrict__ x, float* __restrict__ out) {
    int i = blockIdx.x * blockDim.x + threadIdx.x;
    float v = x[i];
    g_y[i]  = v;
    g_yh[i] = __float2half_rn(v);
    int b = i / X_, c = i % X_;
    out[(size_t)b * T_ * X_ + c] = v;
}

__global__ void cvt_kernel(const float* __restrict__ src, __half* __restrict__ dst, int n) {
    int i = blockIdx.x * blockDim.x + threadIdx.x;
    if (i < n) dst[i] = __float2half_rn(src[i]);
}

__global__ void pack_wout_kernel(const float* __restrict__ W_out, __half* __restrict__ wcat) {
    int i = blockIdx.x * blockDim.x + threadIdx.x;    // 1024*256
    int k = i >> 8, n = i & 255;
    wcat[k * 1280 + n] = __float2half_rn(W_out[k * 256 + n]);
}

__global__ void bcat_kernel(const float* __restrict__ b_out, const float* __restrict__ W_in,
                            float* __restrict__ bcat) {
    int n = blockIdx.x * blockDim.x + threadIdx.x;
    if (n >= 1280) return;
    if (n < 256) bcat[n] = b_out[n];
    else {
        int c = n - 256;
        float s = 0.f;
        for (int k = 0; k < 256; k++) s += b_out[k] * W_in[k * 1024 + c];
        bcat[n] = s;
    }
}

// ---------------- raw-mma fp16 GEMM, register epilogue ----------------
// MODE 0: CoutH = tanh(val + bias)
// MODE 1: fused: bn<256 -> y += dt*val_b, store out; else h0f += dt*val_b, a = tanh
// MODE 2: CoutH = val (no bias)
// MODE 3: h0f = val + bias; a = tanh
template <int TBM, int MODE>
__global__ void __launch_bounds__(256, 1) gemm_k(
    const __half* __restrict__ A, const __half* __restrict__ W,
    const float* __restrict__ bias, __half* __restrict__ CoutH,
    int K, int N, int ldc,
    float* __restrict__ gy, float* __restrict__ h0f, __half* __restrict__ aout,
    float* __restrict__ outp, const float* __restrict__ ts, int t)
{
    extern __shared__ __half smem[];
    constexpr int AST = TBM * ALD;
    constexpr int SH  = AST + BST;            // halves per stage
    constexpr int NB  = (TBM == 32) ? 2 : 4;  // n8-mmas per warp
    constexpr int WT  = NB * 8;               // warp tile n-width (16/32)

    const int tid  = threadIdx.x;
    const int lane = tid & 31;
    const int w    = tid >> 5;
    const int wm   = (TBM == 32) ? (w & 1) : (w & 3);
    const int wn   = (TBM == 32) ? (w >> 1) : (w >> 2);
    const int bm   = blockIdx.y * TBM;
    const int bn   = blockIdx.x * BN;

    const uint32_t sbase = (uint32_t)__cvta_generic_to_shared(smem);

    float cacc[NB][4];
    #pragma unroll
    for (int i = 0; i < NB; i++)
        #pragma unroll
        for (int j = 0; j < 4; j++) cacc[i][j] = 0.0f;

    const int NIT = K / BK;

    auto loadStage = [&](int it) {
        if (it < NIT) {
            const int k0 = it * BK;
            uint32_t asb = sbase + (uint32_t)((it % NSTG) * SH) * 2;
            uint32_t bsb = asb + AST * 2;
            constexpr int ACH = TBM * BK / 8 / 256;   // 2 (TBM=32) / 4 (TBM=64)
            #pragma unroll
            for (int i = 0; i < ACH; i++) {
                int id = tid + i * 256;
                int r = id >> 4, c8 = id & 15;        // 16 chunks of 8 halves per A row
                CP16(asb + (uint32_t)(r * ALD + c8 * 8) * 2,
                     A + (size_t)(bm + r) * K + k0 + c8 * 8);
            }
            #pragma unroll
            for (int i = 0; i < 4; i++) {             // B: 128 rows x 8 chunks
                int id = tid + i * 256;
                int r = id >> 3, c8 = id & 7;
                CP16(bsb + (uint32_t)(r * BLD + c8 * 8) * 2,
                     W + (size_t)(k0 + r) * N + bn + c8 * 8);
            }
        }
        CP_COMMIT();
    };

    loadStage(0); loadStage(1); loadStage(2);

    // per-lane ldmatrix base offsets (halves)
    const int a_off = (wm * 16 + (lane & 15)) * ALD + (lane >> 4) * 8;
    const int b_off = (lane & 15) * BLD + wn * WT + (lane >> 4) * 8;

    for (int it = 0; it < NIT; it++) {
        CP_WAIT2();
        __syncthreads();

        uint32_t abase = sbase + (uint32_t)((it % NSTG) * SH) * 2;
        uint32_t bbase = abase + AST * 2;
        uint32_t arow = abase + (uint32_t)a_off * 2;
        uint32_t brow = bbase + (uint32_t)b_off * 2;

        #pragma unroll
        for (int kf = 0; kf < BK / 16; kf++) {
            uint32_t a[4];
            ldsm_x4(a, arow + kf * 32);               // +16 halves per kf
            #pragma unroll
            for (int nb2 = 0; nb2 < NB / 2; nb2++) {
                uint32_t b[4];
                ldsm_x4t(b, brow + (uint32_t)(kf * 16 * BLD + nb2 * 16) * 2);
                mma16816(cacc[nb2 * 2 + 0], a, b[0], b[1]);
                mma16816(cacc[nb2 * 2 + 1], a, b[2], b[3]);
            }
        }
        loadStage(it + NSTG - 1);
    }

    // ---- register epilogue (known m16n8 layout) ----
    const int r0  = bm + wm * 16 + (lane >> 2);   // row of c0,c1 ; +8 for c2,c3
    const int c2  = (lane & 3) * 2;

    if (MODE == 1) {
        const float dt = ts[t + 1] - ts[t];
        #pragma unroll
        for (int nb = 0; nb < NB; nb++) {
            const int col = bn + wn * WT + nb * 8 + c2;
            float2 bv = *reinterpret_cast<const float2*>(&bias[col]);
            float v00 = cacc[nb][0] + bv.x, v01 = cacc[nb][1] + bv.y;
            float v10 = cacc[nb][2] + bv.x, v11 = cacc[nb][3] + bv.y;
            if (bn < 256) {
                int yi0 = r0 * X_ + col, yi1 = (r0 + 8) * X_ + col;
                float2 y0 = *reinterpret_cast<float2*>(&gy[yi0]);
                float2 y1 = *reinterpret_cast<float2*>(&gy[yi1]);
                y0.x += dt * v00; y0.y += dt * v01;
                y1.x += dt * v10; y1.y += dt * v11;
                *reinterpret_cast<float2*>(&gy[yi0]) = y0;
                *reinterpret_cast<float2*>(&gy[yi1]) = y1;
                size_t ob = (size_t)(t + 1) * X_ + col;
                *reinterpret_cast<float2*>(&outp[(size_t)r0 * T_ * X_ + ob]) = y0;
                *reinterpret_cast<float2*>(&outp[(size_t)(r0 + 8) * T_ * X_ + ob]) = y1;
            } else {
                int hi0 = r0 * H_ + (col - 256), hi1 = (r0 + 8) * H_ + (col - 256);
                float2 h0v = *reinterpret_cast<float2*>(&h0f[hi0]);
                float2 h1v = *reinterpret_cast<float2*>(&h0f[hi1]);
                h0v.x += dt * v00; h0v.y += dt * v01;
                h1v.x += dt * v10; h1v.y += dt * v11;
                *reinterpret_cast<float2*>(&h0f[hi0]) = h0v;
                *reinterpret_cast<float2*>(&h0f[hi1]) = h1v;
                __half2 p0 = __halves2half2(__float2half_rn(tanhfast(h0v.x)),
                                            __float2half_rn(tanhfast(h0v.y)));
                __half2 p1 = __halves2half2(__float2half_rn(tanhfast(h1v.x)),
                                            __float2half_rn(tanhfast(h1v.y)));
                *reinterpret_cast<__half2*>(&aout[hi0]) = p0;
                *reinterpret_cast<__half2*>(&aout[hi1]) = p1;
            }
        }
    } else if (MODE == 0) {
        #pragma unroll
        for (int nb = 0; nb < NB; nb++) {
            const int col = bn + wn * WT + nb * 8 + c2;
            float2 bv = *reinterpret_cast<const float2*>(&bias[col]);
            __half2 p0 = __halves2half2(__float2half_rn(tanhfast(cacc[nb][0] + bv.x)),
                                        __float2half_rn(tanhfast(cacc[nb][1] + bv.y)));
            __half2 p1 = __halves2half2(__float2half_rn(tanhfast(cacc[nb][2] + bv.x)),
                                        __float2half_rn(tanhfast(cacc[nb][3] + bv.y)));
            *reinterpret_cast<__half2*>(&CoutH[(size_t)r0 * ldc + col]) = p0;
            *reinterpret_cast<__half2*>(&CoutH[(size_t)(r0 + 8) * ldc + col]) = p1;
        }
    } else if (MODE == 2) {
        #pragma unroll
        for (int nb = 0; nb < NB; nb++) {
            const int col = bn + wn * WT + nb * 8 + c2;
            __half2 p0 = __halves2half2(__float2half_rn(cacc[nb][0]),
                                        __float2half_rn(cacc[nb][1]));
            __half2 p1 = __halves2half2(__float2half_rn(cacc[nb][2]),
                                        __float2half_rn(cacc[nb][3]));
            *reinterpret_cast<__half2*>(&CoutH[(size_t)r0 * ldc + col]) = p0;
            *reinterpret_cast<__half2*>(&CoutH[(size_t)(r0 + 8) * ldc + col]) = p1;
        }
    } else {  // MODE 3
        #pragma unroll
        for (int nb = 0; nb < NB; nb++) {
            const int col = bn + wn * WT + nb * 8 + c2;
            float2 bv = *reinterpret_cast<const float2*>(&bias[col]);
            float v00 = cacc[nb][0] + bv.x, v01 = cacc[nb][1] + bv.y;
            float v10 = cacc[nb][2] + bv.x, v11 = cacc[nb][3] + bv.y;
            int hi0 = r0 * ldc + col, hi1 = (r0 + 8) * ldc + col;
            *reinterpret_cast<float2*>(&h0f[hi0]) = make_float2(v00, v01);
            *reinterpret_cast<float2*>(&h0f[hi1]) = make_float2(v10, v11);
            __half2 p0 = __halves2half2(__float2half_rn(tanhfast(v00)),
                                        __float2half_rn(tanhfast(v01)));
            __half2 p1 = __halves2half2(__float2half_rn(tanhfast(v10)),
                                        __float2half_rn(tanhfast(v11)));
            *reinterpret_cast<__half2*>(&aout[hi0]) = p0;
            *reinterpret_cast<__half2*>(&aout[hi1]) = p1;
        }
    }
}

#define SMEM_OF(TBM) (NSTG * ((TBM) * ALD + BST) * 2)

// ---------------- host ----------------
extern "C" void kernel_launch(void* const* d_in, const int* in_sizes, int n_in,
                              void* d_out, int out_size)
{
    const float* x     = (const float*)d_in[0];
    const float* ts    = (const float*)d_in[1];
    const float* W_in  = (const float*)d_in[2];
    const float* b_in  = (const float*)d_in[3];
    const float* W_h   = (const float*)d_in[4];
    const float* b_h   = (const float*)d_in[5];
    const float* W_out = (const float*)d_in[6];
    const float* b_out = (const float*)d_in[7];
    float* out = (float*)d_out;

    float  *py, *ph0f, *pbcat;
    __half *pyh, *pa, *pb1, *pb2, *pb3, *pwh;
    cudaGetSymbolAddress((void**)&py,   g_y);
    cudaGetSymbolAddress((void**)&pyh,  g_yh);
    cudaGetSymbolAddress((void**)&ph0f, g_h0f);
    cudaGetSymbolAddress((void**)&pa,   g_a);
    cudaGetSymbolAddress((void**)&pb1,  g_b1);
    cudaGetSymbolAddress((void**)&pb2,  g_b2);
    cudaGetSymbolAddress((void**)&pb3,  g_b3);
    cudaGetSymbolAddress((void**)&pbcat, g_bcat);
    cudaGetSymbolAddress((void**)&pwh,  g_wh);

    constexpr int SM_H = SMEM_OF(32);   // 108544
    constexpr int SM_F = SMEM_OF(64);   // 143360

    cudaFuncSetAttribute(gemm_k<32, 0>, cudaFuncAttributeMaxDynamicSharedMemorySize, SM_H);
    cudaFuncSetAttribute(gemm_k<64, 1>, cudaFuncAttributeMaxDynamicSharedMemorySize, SM_F);
    cudaFuncSetAttribute(gemm_k<32, 2>, cudaFuncAttributeMaxDynamicSharedMemorySize, SM_H);
    cudaFuncSetAttribute(gemm_k<32, 3>, cudaFuncAttributeMaxDynamicSharedMemorySize, SM_H);

    // ---- one-time setup ----
    cvt_kernel<<<(256 * 1024 + 255) / 256, 256>>>(W_in,  pwh + WH_IN,   256 * 1024);
    cvt_kernel<<<(3 * 1024 * 1024 + 255) / 256, 256>>>(W_h, pwh + WH_H, 3 * 1024 * 1024);
    cvt_kernel<<<(1024 * 256 + 255) / 256, 256>>>(W_out, pwh + WH_OUTA, 1024 * 256);
    pack_wout_kernel<<<1024, 256>>>(W_out, pwh + WH_CAT);
    bcat_kernel<<<5, 256>>>(b_out, W_in, pbcat);

    // W_combo = W_out @ W_in -> W_cat columns [256, 1280)
    gemm_k<32, 2><<<dim3(16, 32), 256, SM_H>>>(
        pwh + WH_OUTA, pwh + WH_IN, (const float*)nullptr, pwh + WH_CAT + 256,
        256, 1024, 1280,
        (float*)nullptr, (float*)nullptr, (__half*)nullptr, (float*)nullptr,
        (const float*)nullptr, 0);

    node_init_kernel<<<(B_ * X_) / 256, 256>>>(x, out);

    // h0f = x @ W_in + b_in ; a = tanh(h0f)
    gemm_k<32, 3><<<dim3(16, 8), 256, SM_H>>>(
        pyh, pwh + WH_IN, b_in, (__half*)nullptr,
        256, 1024, 1024,
        (float*)nullptr, ph0f, pa, (float*)nullptr, (const float*)nullptr, 0);

    // ---- time loop: 4 plain-launched GEMMs per step ----
    dim3 blk(256);
    dim3 gridH(16, 8);    // hidden: 128 CTAs (TBM=32)
    dim3 gridF(20, 4);    // fused:  80 CTAs (TBM=64), single wave

    const __half* Wh = pwh + WH_H;

    for (int t = 0; t < T_ - 1; t++) {
        gemm_k<32, 0><<<gridH, blk, SM_H>>>(
            pa,  Wh + 0 * 1024 * 1024, b_h + 0 * H_, pb1, 1024, 1024, 1024,
            (float*)nullptr, (float*)nullptr, (__half*)nullptr, (float*)nullptr,
            (const float*)nullptr, 0);
        gemm_k<32, 0><<<gridH, blk, SM_H>>>(
            pb1, Wh + 1 * 1024 * 1024, b_h + 1 * H_, pb2, 1024, 1024, 1024,
            (float*)nullptr, (float*)nullptr, (__half*)nullptr, (float*)nullptr,
            (const float*)nullptr, 0);
        gemm_k<32, 0><<<gridH, blk, SM_H>>>(
            pb2, Wh + 2 * 1024 * 1024, b_h + 2 * H_, pb3, 1024, 1024, 1024,
            (float*)nullptr, (float*)nullptr, (__half*)nullptr, (float*)nullptr,
            (const float*)nullptr, 0);
        gemm_k<64, 1><<<gridF, blk, SM_F>>>(
            pb3, pwh + WH_CAT, pbcat, (__half*)nullptr, 1024, 1280, 0,
            py, ph0f, pa, out, ts, t);
    }
}

// round 15
// speedup vs baseline: 1.0650x; 1.0219x over previous
#include <cuda_runtime.h>
#include <cuda_fp16.h>
#include <cstdint>
#include <math.h>

#define B_  256
#define T_  128
#define X_  256
#define H_  1024

#define BN  64
#define BK  128
#define NSTG 4
#define ALD (BK + 8)                  // 136 halves
#define BLD (BN + 8)                  // 72 halves
#define BST (BK * BLD)                // 9216 halves

// ---------------- device scratch ----------------
__device__ float  g_y   [B_ * X_];
__device__ __half g_yh  [B_ * X_];
__device__ float  g_h0f [B_ * H_];
__device__ __half g_a   [B_ * H_];
__device__ __half g_b1  [B_ * H_];
__device__ __half g_b2  [B_ * H_];
__device__ __half g_b3a [B_ * H_];
__device__ __half g_b3b [B_ * H_];
__device__ float  g_bcat[1280];

#define WH_IN   0
#define WH_H    (256 * 1024)
#define WH_OUTA (WH_H + 3 * 1024 * 1024)
#define WH_CAT  (WH_OUTA + 1024 * 256)
#define WH_TOT  (WH_CAT + 1024 * 1280)
__device__ __half g_wh[WH_TOT];

#define CP16(dst, src) \
    asm volatile("cp.async.cg.shared.global [%0], [%1], 16;" :: "r"(dst), "l"(src))
#define CP_COMMIT() asm volatile("cp.async.commit_group;" ::: "memory")
#define CP_WAIT2()  asm volatile("cp.async.wait_group 2;" ::: "memory")

__device__ __forceinline__ float tanhfast(float x) {
    float y;
    asm("tanh.approx.f32 %0, %1;" : "=f"(y) : "f"(x));
    return y;
}

__device__ __forceinline__ void ldsm_x4(uint32_t (&d)[4], uint32_t addr) {
    asm volatile("ldmatrix.sync.aligned.m8n8.x4.shared.b16 {%0,%1,%2,%3}, [%4];"
        : "=r"(d[0]), "=r"(d[1]), "=r"(d[2]), "=r"(d[3]) : "r"(addr));
}
__device__ __forceinline__ void ldsm_x4t(uint32_t (&d)[4], uint32_t addr) {
    asm volatile("ldmatrix.sync.aligned.m8n8.x4.trans.shared.b16 {%0,%1,%2,%3}, [%4];"
        : "=r"(d[0]), "=r"(d[1]), "=r"(d[2]), "=r"(d[3]) : "r"(addr));
}
__device__ __forceinline__ void mma16816(float (&c)[4], const uint32_t (&a)[4],
                                         uint32_t b0, uint32_t b1) {
    asm volatile("mma.sync.aligned.m16n8k16.row.col.f32.f16.f16.f32 "
        "{%0,%1,%2,%3}, {%4,%5,%6,%7}, {%8,%9}, {%0,%1,%2,%3};"
        : "+f"(c[0]), "+f"(c[1]), "+f"(c[2]), "+f"(c[3])
        : "r"(a[0]), "r"(a[1]), "r"(a[2]), "r"(a[3]), "r"(b0), "r"(b1));
}

// ---------------- setup kernels ----------------
__global__ void node_init_kernel(const float* __restrict__ x, float* __restrict__ out) {
    int i = blockIdx.x * blockDim.x + threadIdx.x;
    float v = x[i];
    g_y[i]  = v;
    g_yh[i] = __float2half_rn(v);
    int b = i / X_, c = i % X_;
    out[(size_t)b * T_ * X_ + c] = v;
}

__global__ void cvt_kernel(const float* __restrict__ src, __half* __restrict__ dst, int n) {
    int i = blockIdx.x * blockDim.x + threadIdx.x;
    if (i < n) dst[i] = __float2half_rn(src[i]);
}

__global__ void pack_wout_kernel(const float* __restrict__ W_out, __half* __restrict__ wcat) {
    int i = blockIdx.x * blockDim.x + threadIdx.x;    // 1024*256
    int k = i >> 8, n = i & 255;
    wcat[k * 1280 + n] = __float2half_rn(W_out[k * 256 + n]);
}

__global__ void bcat_kernel(const float* __restrict__ b_out, const float* __restrict__ W_in,
                            float* __restrict__ bcat) {
    int n = blockIdx.x * blockDim.x + threadIdx.x;
    if (n >= 1280) return;
    if (n < 256) bcat[n] = b_out[n];
    else {
        int c = n - 256;
        float s = 0.f;
        for (int k = 0; k < 256; k++) s += b_out[k] * W_in[k * 1024 + c];
        bcat[n] = s;
    }
}

// ---------------- raw-mma fp16 GEMM, register epilogue ----------------
// MODE 0: CoutH = tanh(val + bias)       (hidden)
// MODE 2: CoutH = val (no bias)          (combo setup)
// MODE 3: h0f = val + bias; a = tanh     (initial in-layer)
// MODE 4: h0f += dt*(val+bias); a = tanh (critical recurrence half of out-layer)
// MODE 5: y += dt*(val+bias); out store  (off-path output half)
template <int TBM, int MODE>
__global__ void __launch_bounds__(256, 1) gemm_k(
    const __half* __restrict__ A, const __half* __restrict__ W,
    const float* __restrict__ bias, __half* __restrict__ CoutH,
    int K, int N, int ldc,
    float* __restrict__ gy, float* __restrict__ h0f, __half* __restrict__ aout,
    float* __restrict__ outp, const float* __restrict__ ts, int t)
{
    extern __shared__ __half smem[];
    constexpr int AST = TBM * ALD;
    constexpr int SH  = AST + BST;            // halves per stage
    constexpr int NB  = (TBM == 32) ? 2 : 4;  // n8-mmas per warp
    constexpr int WT  = NB * 8;               // warp tile n-width (16/32)

    const int tid  = threadIdx.x;
    const int lane = tid & 31;
    const int w    = tid >> 5;
    const int wm   = (TBM == 32) ? (w & 1) : (w & 3);
    const int wn   = (TBM == 32) ? (w >> 1) : (w >> 2);
    const int bm   = blockIdx.y * TBM;
    const int bn   = blockIdx.x * BN;

    const uint32_t sbase = (uint32_t)__cvta_generic_to_shared(smem);

    float cacc[NB][4];
    #pragma unroll
    for (int i = 0; i < NB; i++)
        #pragma unroll
        for (int j = 0; j < 4; j++) cacc[i][j] = 0.0f;

    const int NIT = K / BK;

    auto loadStage = [&](int it) {
        if (it < NIT) {
            const int k0 = it * BK;
            uint32_t asb = sbase + (uint32_t)((it % NSTG) * SH) * 2;
            uint32_t bsb = asb + AST * 2;
            constexpr int ACH = TBM * BK / 8 / 256;
            #pragma unroll
            for (int i = 0; i < ACH; i++) {
                int id = tid + i * 256;
                int r = id >> 4, c8 = id & 15;
                CP16(asb + (uint32_t)(r * ALD + c8 * 8) * 2,
                     A + (size_t)(bm + r) * K + k0 + c8 * 8);
            }
            #pragma unroll
            for (int i = 0; i < 4; i++) {
                int id = tid + i * 256;
                int r = id >> 3, c8 = id & 7;
                CP16(bsb + (uint32_t)(r * BLD + c8 * 8) * 2,
                     W + (size_t)(k0 + r) * N + bn + c8 * 8);
            }
        }
        CP_COMMIT();
    };

    loadStage(0); loadStage(1); loadStage(2);

    const int a_off = (wm * 16 + (lane & 15)) * ALD + (lane >> 4) * 8;
    const int b_off = (lane & 15) * BLD + wn * WT + (lane >> 4) * 8;

    for (int it = 0; it < NIT; it++) {
        CP_WAIT2();
        __syncthreads();

        uint32_t abase = sbase + (uint32_t)((it % NSTG) * SH) * 2;
        uint32_t arow = abase + (uint32_t)a_off * 2;
        uint32_t brow = abase + AST * 2 + (uint32_t)b_off * 2;

        #pragma unroll
        for (int kf = 0; kf < BK / 16; kf++) {
            uint32_t a[4];
            ldsm_x4(a, arow + kf * 32);
            #pragma unroll
            for (int nb2 = 0; nb2 < NB / 2; nb2++) {
                uint32_t b[4];
                ldsm_x4t(b, brow + (uint32_t)(kf * 16 * BLD + nb2 * 16) * 2);
                mma16816(cacc[nb2 * 2 + 0], a, b[0], b[1]);
                mma16816(cacc[nb2 * 2 + 1], a, b[2], b[3]);
            }
        }
        loadStage(it + NSTG - 1);
    }

    // ---- register epilogue (m16n8 layout: rows lane>>2 / +8, cols (lane&3)*2) ----
    const int r0 = bm + wm * 16 + (lane >> 2);
    const int c2 = (lane & 3) * 2;

    if (MODE == 0) {
        #pragma unroll
        for (int nb = 0; nb < NB; nb++) {
            const int col = bn + wn * WT + nb * 8 + c2;
            float2 bv = *reinterpret_cast<const float2*>(&bias[col]);
            __half2 p0 = __halves2half2(__float2half_rn(tanhfast(cacc[nb][0] + bv.x)),
                                        __float2half_rn(tanhfast(cacc[nb][1] + bv.y)));
            __half2 p1 = __halves2half2(__float2half_rn(tanhfast(cacc[nb][2] + bv.x)),
                                        __float2half_rn(tanhfast(cacc[nb][3] + bv.y)));
            *reinterpret_cast<__half2*>(&CoutH[(size_t)r0 * ldc + col]) = p0;
            *reinterpret_cast<__half2*>(&CoutH[(size_t)(r0 + 8) * ldc + col]) = p1;
        }
    } else if (MODE == 2) {
        #pragma unroll
        for (int nb = 0; nb < NB; nb++) {
            const int col = bn + wn * WT + nb * 8 + c2;
            __half2 p0 = __halves2half2(__float2half_rn(cacc[nb][0]),
                                        __float2half_rn(cacc[nb][1]));
            __half2 p1 = __halves2half2(__float2half_rn(cacc[nb][2]),
                                        __float2half_rn(cacc[nb][3]));
            *reinterpret_cast<__half2*>(&CoutH[(size_t)r0 * ldc + col]) = p0;
            *reinterpret_cast<__half2*>(&CoutH[(size_t)(r0 + 8) * ldc + col]) = p1;
        }
    } else if (MODE == 3) {
        #pragma unroll
        for (int nb = 0; nb < NB; nb++) {
            const int col = bn + wn * WT + nb * 8 + c2;
            float2 bv = *reinterpret_cast<const float2*>(&bias[col]);
            float v00 = cacc[nb][0] + bv.x, v01 = cacc[nb][1] + bv.y;
            float v10 = cacc[nb][2] + bv.x, v11 = cacc[nb][3] + bv.y;
            int hi0 = r0 * ldc + col, hi1 = (r0 + 8) * ldc + col;
            *reinterpret_cast<float2*>(&h0f[hi0]) = make_float2(v00, v01);
            *reinterpret_cast<float2*>(&h0f[hi1]) = make_float2(v10, v11);
            __half2 p0 = __halves2half2(__float2half_rn(tanhfast(v00)),
                                        __float2half_rn(tanhfast(v01)));
            __half2 p1 = __halves2half2(__float2half_rn(tanhfast(v10)),
                                        __float2half_rn(tanhfast(v11)));
            *reinterpret_cast<__half2*>(&aout[hi0]) = p0;
            *reinterpret_cast<__half2*>(&aout[hi1]) = p1;
        }
    } else if (MODE == 4) {
        const float dt = ts[t + 1] - ts[t];
        #pragma unroll
        for (int nb = 0; nb < NB; nb++) {
            const int col = bn + wn * WT + nb * 8 + c2;       // 0..1023 (W/bias pre-offset)
            float2 bv = *reinterpret_cast<const float2*>(&bias[col]);
            int hi0 = r0 * H_ + col, hi1 = (r0 + 8) * H_ + col;
            float2 h0v = *reinterpret_cast<float2*>(&h0f[hi0]);
            float2 h1v = *reinterpret_cast<float2*>(&h0f[hi1]);
            h0v.x += dt * (cacc[nb][0] + bv.x); h0v.y += dt * (cacc[nb][1] + bv.y);
            h1v.x += dt * (cacc[nb][2] + bv.x); h1v.y += dt * (cacc[nb][3] + bv.y);
            *reinterpret_cast<float2*>(&h0f[hi0]) = h0v;
            *reinterpret_cast<float2*>(&h0f[hi1]) = h1v;
            __half2 p0 = __halves2half2(__float2half_rn(tanhfast(h0v.x)),
                                        __float2half_rn(tanhfast(h0v.y)));
            __half2 p1 = __halves2half2(__float2half_rn(tanhfast(h1v.x)),
                                        __float2half_rn(tanhfast(h1v.y)));
            *reinterpret_cast<__half2*>(&aout[hi0]) = p0;
            *reinterpret_cast<__half2*>(&aout[hi1]) = p1;
        }
    } else {   // MODE 5
        const float dt = ts[t + 1] - ts[t];
        #pragma unroll
        for (int nb = 0; nb < NB; nb++) {
            const int col = bn + wn * WT + nb * 8 + c2;       // 0..255
            float2 bv = *reinterpret_cast<const float2*>(&bias[col]);
            int yi0 = r0 * X_ + col, yi1 = (r0 + 8) * X_ + col;
            float2 y0 = *reinterpret_cast<float2*>(&gy[yi0]);
            float2 y1 = *reinterpret_cast<float2*>(&gy[yi1]);
            y0.x += dt * (cacc[nb][0] + bv.x); y0.y += dt * (cacc[nb][1] + bv.y);
            y1.x += dt * (cacc[nb][2] + bv.x); y1.y += dt * (cacc[nb][3] + bv.y);
            *reinterpret_cast<float2*>(&gy[yi0]) = y0;
            *reinterpret_cast<float2*>(&gy[yi1]) = y1;
            size_t ob = (size_t)(t + 1) * X_ + col;
            *reinterpret_cast<float2*>(&outp[(size_t)r0 * T_ * X_ + ob]) = y0;
            *reinterpret_cast<float2*>(&outp[(size_t)(r0 + 8) * T_ * X_ + ob]) = y1;
        }
    }
}

#define SMEM_OF(TBM) (NSTG * ((TBM) * ALD + BST) * 2)

// ---------------- host ----------------
extern "C" void kernel_launch(void* const* d_in, const int* in_sizes, int n_in,
                              void* d_out, int out_size)
{
    const float* x     = (const float*)d_in[0];
    const float* ts    = (const float*)d_in[1];
    const float* W_in  = (const float*)d_in[2];
    const float* b_in  = (const float*)d_in[3];
    const float* W_h   = (const float*)d_in[4];
    const float* b_h   = (const float*)d_in[5];
    const float* W_out = (const float*)d_in[6];
    const float* b_out = (const float*)d_in[7];
    float* out = (float*)d_out;

    float  *py, *ph0f, *pbcat;
    __half *pyh, *pa, *pb1, *pb2, *pb3a, *pb3b, *pwh;
    cudaGetSymbolAddress((void**)&py,   g_y);
    cudaGetSymbolAddress((void**)&pyh,  g_yh);
    cudaGetSymbolAddress((void**)&ph0f, g_h0f);
    cudaGetSymbolAddress((void**)&pa,   g_a);
    cudaGetSymbolAddress((void**)&pb1,  g_b1);
    cudaGetSymbolAddress((void**)&pb2,  g_b2);
    cudaGetSymbolAddress((void**)&pb3a, g_b3a);
    cudaGetSymbolAddress((void**)&pb3b, g_b3b);
    cudaGetSymbolAddress((void**)&pbcat, g_bcat);
    cudaGetSymbolAddress((void**)&pwh,  g_wh);

    constexpr int SM_H = SMEM_OF(32);   // 108544

    static cudaStream_t s1 = nullptr;
    static cudaEvent_t evA = nullptr, evB[2] = {nullptr, nullptr};
    if (!s1) {
        cudaStreamCreateWithFlags(&s1, cudaStreamNonBlocking);
        cudaEventCreateWithFlags(&evA, cudaEventDisableTiming);
        cudaEventCreateWithFlags(&evB[0], cudaEventDisableTiming);
        cudaEventCreateWithFlags(&evB[1], cudaEventDisableTiming);

        cudaFuncSetAttribute(gemm_k<32, 0>, cudaFuncAttributeMaxDynamicSharedMemorySize, SM_H);
        cudaFuncSetAttribute(gemm_k<32, 2>, cudaFuncAttributeMaxDynamicSharedMemorySize, SM_H);
        cudaFuncSetAttribute(gemm_k<32, 3>, cudaFuncAttributeMaxDynamicSharedMemorySize, SM_H);
        cudaFuncSetAttribute(gemm_k<32, 4>, cudaFuncAttributeMaxDynamicSharedMemorySize, SM_H);
        cudaFuncSetAttribute(gemm_k<32, 5>, cudaFuncAttributeMaxDynamicSharedMemorySize, SM_H);
    }

    // ---- one-time setup ----
    cvt_kernel<<<(256 * 1024 + 255) / 256, 256>>>(W_in,  pwh + WH_IN,   256 * 1024);
    cvt_kernel<<<(3 * 1024 * 1024 + 255) / 256, 256>>>(W_h, pwh + WH_H, 3 * 1024 * 1024);
    cvt_kernel<<<(1024 * 256 + 255) / 256, 256>>>(W_out, pwh + WH_OUTA, 1024 * 256);
    pack_wout_kernel<<<1024, 256>>>(W_out, pwh + WH_CAT);
    bcat_kernel<<<5, 256>>>(b_out, W_in, pbcat);

    // W_combo = W_out @ W_in -> W_cat columns [256, 1280)
    gemm_k<32, 2><<<dim3(16, 32), 256, SM_H>>>(
        pwh + WH_OUTA, pwh + WH_IN, (const float*)nullptr, pwh + WH_CAT + 256,
        256, 1024, 1280,
        (float*)nullptr, (float*)nullptr, (__half*)nullptr, (float*)nullptr,
        (const float*)nullptr, 0);

    node_init_kernel<<<(B_ * X_) / 256, 256>>>(x, out);

    // h0f = x @ W_in + b_in ; a = tanh(h0f)
    gemm_k<32, 3><<<dim3(16, 8), 256, SM_H>>>(
        pyh, pwh + WH_IN, b_in, (__half*)nullptr,
        256, 1024, 1024,
        (float*)nullptr, ph0f, pa, (float*)nullptr, (const float*)nullptr, 0);

    // ---- time loop ----
    dim3 blk(256);
    dim3 gridH(16, 8);    // N=1024 -> 128 CTAs
    dim3 gridY(4, 8);     // N=256  -> 32 CTAs

    const __half* Wh = pwh + WH_H;
    __half* b3s[2] = {pb3a, pb3b};

    for (int t = 0; t < T_ - 1; t++) {
        __half* pb3 = b3s[t & 1];
        // protect b3[t&1] against y(t-2) still reading it
        if (t >= 2) cudaStreamWaitEvent(0, evB[t & 1], 0);

        gemm_k<32, 0><<<gridH, blk, SM_H>>>(
            pa,  Wh + 0 * 1024 * 1024, b_h + 0 * H_, pb1, 1024, 1024, 1024,
            (float*)nullptr, (float*)nullptr, (__half*)nullptr, (float*)nullptr,
            (const float*)nullptr, 0);
        gemm_k<32, 0><<<gridH, blk, SM_H>>>(
            pb1, Wh + 1 * 1024 * 1024, b_h + 1 * H_, pb2, 1024, 1024, 1024,
            (float*)nullptr, (float*)nullptr, (__half*)nullptr, (float*)nullptr,
            (const float*)nullptr, 0);
        gemm_k<32, 0><<<gridH, blk, SM_H>>>(
            pb2, Wh + 2 * 1024 * 1024, b_h + 2 * H_, pb3, 1024, 1024, 1024,
            (float*)nullptr, (float*)nullptr, (__half*)nullptr, (float*)nullptr,
            (const float*)nullptr, 0);
        cudaEventRecord(evA, 0);

        // critical: h0f recurrence (columns 256..1279 of Wcat)
        gemm_k<32, 4><<<gridH, blk, SM_H>>>(
            pb3, pwh + WH_CAT + 256, pbcat + 256, (__half*)nullptr,
            1024, 1280, 0,
            (float*)nullptr, ph0f, pa, (float*)nullptr, ts, t);

        // off-path: y update + output store (columns 0..255 of Wcat)
        cudaStreamWaitEvent(s1, evA, 0);
        gemm_k<32, 5><<<gridY, blk, SM_H, s1>>>(
            pb3, pwh + WH_CAT, pbcat, (__half*)nullptr,
            1024, 1280, 0,
            py, (float*)nullptr, (__half*)nullptr, out, ts, t);
        cudaEventRecord(evB[t & 1], s1);
    }

    // join side stream back into the capture stream
    cudaStreamWaitEvent(0, evB[(T_ - 2) & 1], 0);
}